// round 10
// baseline (speedup 1.0000x reference)
#include <cuda_runtime.h>
#include <math.h>

#define BB   32
#define SS   512
#define HH   512
#define EE   512
#define TCHUNK 64
#define NTHR 512

// ---------- global scratch ----------
__device__ float g_embg[(size_t)SS * 128 * 16 * BB];    // [t][bid(128)][r(16)][b32]
// tagged h pairs per chain: [chain][buf][jpair(256)][b8]
__device__ unsigned long long g_htag[4][2][256][8];

union F2U { unsigned long long u; float2 f; };

__device__ __forceinline__ unsigned long long ffma2u(unsigned long long a,
                                                     unsigned long long b,
                                                     unsigned long long c) {
    unsigned long long d;
    asm("fma.rn.f32x2 %0, %1, %2, %3;" : "=l"(d) : "l"(a), "l"(b), "l"(c));
    return d;
}

__device__ __forceinline__ unsigned long long ld_rlx(const unsigned long long* p) {
    unsigned long long v;
    asm volatile("ld.relaxed.gpu.b64 %0, [%1];" : "=l"(v) : "l"(p) : "memory");
    return v;
}
__device__ __forceinline__ void st_rlx(unsigned long long* p, unsigned long long v) {
    asm volatile("st.relaxed.gpu.b64 [%0], %1;" :: "l"(p), "l"(v) : "memory");
}

__device__ __forceinline__ float sigmoidf_(float x) {
    return 1.0f / (1.0f + expf(-x));
}

// ======================================================================
// Phase 1: emb_gates (R6/R8 structure, coalesced smem-staged embeddings)
// grid (64 rowpairs, 8 tchunks) x 512 threads. Also clears g_htag.
// ======================================================================
#define P1_OFF_W    0          // 32*256 u64 = 65536
#define P1_OFF_PART 65536      // 16*32*32 f32 = 65536
#define P1_OFF_X    131072     // 256*33 u64 = 67584
#define P1_OFF_SEQ  198656     // 64*32 int = 8192
#define P1_SMEM     206848

__global__ __launch_bounds__(NTHR, 1)
void embg_kernel(const int* __restrict__ seq,
                 const float* __restrict__ emb_table,
                 const float* __restrict__ W_ih)
{
    extern __shared__ char smem[];
    unsigned long long* w2_sh  = (unsigned long long*)(smem + P1_OFF_W);
    float*              partf  = (float*)(smem + P1_OFF_PART);
    unsigned long long* x_sh   = (unsigned long long*)(smem + P1_OFF_X);
    int*                seq_sh = (int*)(smem + P1_OFF_SEQ);

    const int tid = threadIdx.x;
    const int ks  = tid >> 5;
    const int b   = tid & 31;
    const int rbp = blockIdx.x;
    const int t0  = blockIdx.y * TCHUNK;

    // clear tagged h buffers (valid bit -> 0): 4*2*256*8 = 16384 u64 words
    if (blockIdx.y == 0) {
        int n = rbp * NTHR + tid;
        if (n < 4 * 2 * 256 * 8) ((unsigned long long*)g_htag)[n] = 0ull;
    }

    for (int idx = tid; idx < 32 * 256; idx += NTHR) {
        int r  = idx >> 8;
        int kp = idx & 255;
        int grow = (r >> 3) * HH + rbp * 8 + (r & 7);
        w2_sh[idx] = ((const unsigned long long*)(W_ih + (size_t)grow * (EE + HH)))[kp];
    }
    for (int i = tid; i < TCHUNK * BB; i += NTHR) {
        int tl = i >> 5, r = i & 31;
        seq_sh[i] = seq[r * SS + t0 + tl];
    }
    __syncthreads();

    #pragma unroll
    for (int i = 0; i < 16; i++) {
        int n  = i * NTHR + tid;
        int r  = n >> 8;
        int kp = n & 255;
        int token = seq_sh[r];
        x_sh[kp * 33 + r] = __ldg(
            (const unsigned long long*)(emb_table + (size_t)token * EE) + kp);
    }
    __syncthreads();

    for (int tl = 0; tl < TCHUNK; tl++) {
        unsigned long long preg[16];
        if (tl + 1 < TCHUNK) {
            #pragma unroll
            for (int i = 0; i < 16; i++) {
                int n  = i * NTHR + tid;
                int r  = n >> 8;
                int kp = n & 255;
                int token = seq_sh[(tl + 1) * BB + r];
                preg[i] = __ldg(
                    (const unsigned long long*)(emb_table + (size_t)token * EE) + kp);
            }
        }

        unsigned long long x[16];
        #pragma unroll
        for (int i = 0; i < 16; i++) x[i] = x_sh[(ks * 16 + i) * 33 + b];

        #pragma unroll
        for (int p = 0; p < 2; p++) {
            unsigned long long acc[16];
            #pragma unroll
            for (int r = 0; r < 16; r++) acc[r] = 0ull;
            #pragma unroll
            for (int i2 = 0; i2 < 8; i2++) {
                unsigned long long xa = x[2 * i2], xb = x[2 * i2 + 1];
                #pragma unroll
                for (int r = 0; r < 16; r++) {
                    ulonglong2 wv = *(const ulonglong2*)
                        (w2_sh + (p * 16 + r) * 256 + ks * 16 + 2 * i2);
                    acc[r] = ffma2u(xa, wv.x, ffma2u(xb, wv.y, acc[r]));
                }
            }
            #pragma unroll
            for (int r = 0; r < 16; r++) {
                F2U a; a.u = acc[r];
                partf[(ks * 32 + p * 16 + r) * BB + b] = a.f.x + a.f.y;
            }
        }
        __syncthreads();

        if (tl + 1 < TCHUNK) {
            #pragma unroll
            for (int i = 0; i < 16; i++) {
                int n  = i * NTHR + tid;
                x_sh[(n & 255) * 33 + (n >> 8)] = preg[i];
            }
        }

        #pragma unroll
        for (int p = 0; p < 2; p++) {
            int rr = p * 16 + ks;
            float s = 0.f;
            #pragma unroll
            for (int kw = 0; kw < 16; kw++) s += partf[(kw * 32 + rr) * BB + b];
            int gate = rr >> 3, jj = rr & 7;
            int bid  = 2 * rbp + (jj >> 2);
            int ko   = gate * 4 + (jj & 3);
            g_embg[((size_t)(t0 + tl) * 128 + bid) * (16 * BB) + ko * BB + b] = s;
        }
        __syncthreads();
    }
}

// ======================================================================
// Phase 2: 4 INDEPENDENT batch chains (8 batches each), 512 CTAs x 128 thr.
// CTA (chain c, bid) owns h[4bid..4bid+3] for chain c. 4 CTAs/SM co-resident
// -> each chain's sync latency hides behind the other chains' FMA.
// ======================================================================
#define PSTRIDE 136            // padded partf row stride (words) for bank-free access
#define P2_OFF_W    0          // 16*256 u64 = 32768
#define P2_OFF_PART 32768      // 16*136 f32 = 8704
#define P2_OFF_CNS  41472      // 16*8 f32 = 512
#define P2_OFF_GSUM 41984      // 512
#define P2_OFF_C0   42496      // 128
#define P2_SMEM     42752

__global__ __launch_bounds__(128, 4)
void lstm_seq_kernel(const float* __restrict__ enc_h,
                     const float* __restrict__ enc_c,
                     const float* __restrict__ W_ih,
                     const float* __restrict__ W_hh,
                     const float* __restrict__ b_ih,
                     const float* __restrict__ b_hh,
                     float* __restrict__ out)
{
    extern __shared__ char smem[];
    unsigned long long* w2_sh = (unsigned long long*)(smem + P2_OFF_W);
    float*              partf = (float*)(smem + P2_OFF_PART);
    float*              cns_sh = (float*)(smem + P2_OFF_CNS);
    float*              gsum   = (float*)(smem + P2_OFF_GSUM);
    float*              c0_sh  = (float*)(smem + P2_OFF_C0);

    const int tid = threadIdx.x;
    const int c   = blockIdx.x >> 7;       // chain 0..3 (>>7 so co-resident CTAs mix chains)
    const int bid = blockIdx.x & 127;
    const int w   = tid >> 5;              // warp 0..3 : K-slice of 128
    const int kq  = (tid >> 3) & 3;        // K-quarter within warp slice
    const int b   = tid & 7;               // batch within chain
    const int rr  = tid >> 3;              // reduce-row 0..15 (for reduce/emb stage)
    const int j0  = bid * 4;
    const int bg0 = c * 8;                 // global batch offset

    // stage W_h rows (pairs 256..511 of each W_ih row): 16 rows x 256 pairs
    for (int idx = tid; idx < 16 * 256; idx += 128) {
        int r  = idx >> 8;
        int kp = idx & 255;
        int grow = (r >> 2) * HH + j0 + (r & 3);
        w2_sh[idx] = ((const unsigned long long*)(W_ih + (size_t)grow * (EE + HH)))[256 + kp];
    }
    if (tid < 32) {
        int jj = tid >> 3, bb = tid & 7;
        c0_sh[jj * 8 + bb] = enc_c[(bg0 + bb) * HH + j0 + jj];
    }
    __syncthreads();

    // const = h0 @ W_hh^T + b_ih + b_hh  (thread (rr,b): one 512-dot, float4)
    {
        int grow = (rr >> 2) * HH + j0 + (rr & 3);
        const float4* h0p = (const float4*)(enc_h + (size_t)(bg0 + b) * HH);
        const float4* wrp = (const float4*)(W_hh + (size_t)grow * HH);
        float s = 0.f;
        #pragma unroll 4
        for (int k4 = 0; k4 < 128; k4++) {
            float4 hv = __ldg(&h0p[k4]);
            float4 wv = __ldg(&wrp[k4]);
            s += hv.x * wv.x + hv.y * wv.y + hv.z * wv.z + hv.w * wv.w;
        }
        cns_sh[rr * 8 + b] = s + b_ih[grow] + b_hh[grow];
    }
    __syncthreads();

    const int part = w * 4 + kq;           // 0..15 partial index

    for (int t = 0; t < SS; t++) {
        // emb-gate contribution for (rr, b): independent of h, issue first
        float embv = __ldcg(&g_embg[((size_t)t * 128 + bid) * (16 * BB)
                                    + rr * BB + bg0 + b]);

        unsigned long long x[16];
        if (t > 0) {
            const unsigned long long* hb = &g_htag[c][(t - 1) & 1][w * 64 + kq * 16][b];
            const unsigned want = 4u | ((unsigned)t & 3u);
            #pragma unroll
            for (int i = 0; i < 16; i++) x[i] = ld_rlx(&hb[i * 8]);
            #pragma unroll
            for (int i = 0; i < 16; i++) {
                while (((unsigned)x[i] & 7u) != want)
                    x[i] = ld_rlx(&hb[i * 8]);
            }
        } else {
            #pragma unroll
            for (int i = 0; i < 16; i++) x[i] = 0ull;
        }

        unsigned long long acc[16];
        #pragma unroll
        for (int r = 0; r < 16; r++) acc[r] = 0ull;
        #pragma unroll
        for (int i2 = 0; i2 < 8; i2++) {
            unsigned long long xa = x[2 * i2], xb = x[2 * i2 + 1];
            #pragma unroll
            for (int r = 0; r < 16; r++) {
                ulonglong2 wv = *(const ulonglong2*)
                    (w2_sh + r * 256 + w * 64 + kq * 16 + 2 * i2);
                acc[r] = ffma2u(xa, wv.x, ffma2u(xb, wv.y, acc[r]));
            }
        }
        #pragma unroll
        for (int r = 0; r < 16; r++) {
            F2U a; a.u = acc[r];
            partf[r * PSTRIDE + part * 8 + b] = a.f.x + a.f.y;
        }
        __syncthreads();   // sync#1: partf ready

        {
            float s = 0.f;
            #pragma unroll
            for (int p = 0; p < 16; p++) s += partf[rr * PSTRIDE + p * 8 + b];
            gsum[rr * 8 + b] = s + cns_sh[rr * 8 + b] + embv;
        }
        __syncthreads();   // sync#2: gsum ready; warps 1-3 go straight to next poll

        // nonlin + publish: warp 0 only (lanes: jj = tid>>3 in 0..3, bb = tid&7)
        if (tid < 32) {
            int jj = tid >> 3, bb = tid & 7;
            float iv = gsum[(0 * 4 + jj) * 8 + bb];
            float fv = gsum[(1 * 4 + jj) * 8 + bb];
            float gv = gsum[(2 * 4 + jj) * 8 + bb];
            float ov = gsum[(3 * 4 + jj) * 8 + bb];
            float ig = sigmoidf_(iv);
            float fg = sigmoidf_(fv);
            float gg = tanhf(gv);
            float og = sigmoidf_(ov);
            float cc = fg * c0_sh[jj * 8 + bb] + ig * gg;
            float hh = og * tanhf(cc);

            // pair with jj^1 partner (lane xor 8), even-jj lane publishes tagged u64
            float other = __shfl_xor_sync(0xffffffffu, hh, 8);
            if ((jj & 1) == 0) {
                unsigned field = 4u | ((unsigned)(t + 1) & 3u);
                unsigned lo = (__float_as_uint(hh) & ~7u) | field;
                unsigned hi = (__float_as_uint(other) & ~7u) | field;
                st_rlx(&g_htag[c][t & 1][2 * bid + (jj >> 1)][bb],
                       (unsigned long long)lo | ((unsigned long long)hi << 32));
            }
            // full-precision output store (off critical path)
            out[(size_t)(bg0 + bb) * (SS * HH) + (size_t)t * HH + j0 + jj] = hh;
        }
        // no end-of-step barrier (partf/gsum reuse protected by sync#1/#2)
    }
}

extern "C" void kernel_launch(void* const* d_in, const int* in_sizes, int n_in,
                              void* d_out, int out_size) {
    const int*   seq   = (const int*)d_in[0];
    // d_in[1] = enc_out : unused
    const float* enc_h = (const float*)d_in[2];
    const float* enc_c = (const float*)d_in[3];
    const float* emb   = (const float*)d_in[4];
    const float* W_ih  = (const float*)d_in[5];
    const float* W_hh  = (const float*)d_in[6];
    const float* b_ih  = (const float*)d_in[7];
    const float* b_hh  = (const float*)d_in[8];
    float* out = (float*)d_out;

    static bool attr_set = false;
    if (!attr_set) {
        cudaFuncSetAttribute(embg_kernel,
                             cudaFuncAttributeMaxDynamicSharedMemorySize, P1_SMEM);
        cudaFuncSetAttribute(lstm_seq_kernel,
                             cudaFuncAttributeMaxDynamicSharedMemorySize, P2_SMEM);
        // all 512 CTAs MUST be co-resident: force max smem carveout
        cudaFuncSetAttribute(lstm_seq_kernel,
                             cudaFuncAttributePreferredSharedMemoryCarveout, 100);
        attr_set = true;
    }

    dim3 g1(64, SS / TCHUNK);
    embg_kernel<<<g1, NTHR, P1_SMEM>>>(seq, emb, W_ih);
    lstm_seq_kernel<<<512, 128, P2_SMEM>>>(enc_h, enc_c, W_ih, W_hh,
                                           b_ih, b_hh, out);
}

// round 11
// speedup vs baseline: 1.7214x; 1.7214x over previous
#include <cuda_runtime.h>
#include <math.h>

#define BB   32
#define SS   512
#define HH   512
#define EE   512
#define JPB  4
#define NTHR 512
#define TCHUNK 64

// ---------- global scratch ----------
__device__ float g_embg[(size_t)SS * 128 * 16 * BB];   // [t][bid(128)][r(16)][b(32)]
__device__ unsigned long long g_ht2[2][256][BB];        // [buf][jpair][b]
__device__ unsigned g_gen;

union F2U { unsigned long long u; float2 f; };

__device__ __forceinline__ unsigned long long ffma2u(unsigned long long a,
                                                     unsigned long long b,
                                                     unsigned long long c) {
    unsigned long long d;
    asm("fma.rn.f32x2 %0, %1, %2, %3;" : "=l"(d) : "l"(a), "l"(b), "l"(c));
    return d;
}

__device__ __forceinline__ unsigned ld_acq(const unsigned* p) {
    unsigned v;
    asm volatile("ld.global.acquire.gpu.u32 %0, [%1];" : "=r"(v) : "l"(p) : "memory");
    return v;
}
__device__ __forceinline__ void red_release_add(unsigned* p, unsigned v) {
    asm volatile("red.release.gpu.global.add.u32 [%0], %1;" :: "l"(p), "r"(v) : "memory");
}

__device__ __forceinline__ float sigmoidf_(float x) {
    return 1.0f / (1.0f + expf(-x));
}

// ======================================================================
// Phase 1 (R8-measured best): emb_gates, 32 rows/CTA, coalesced smem-staged
// embeddings. grid (64 rowpairs, 8 tchunks) x 512 threads. Resets g_gen.
// ======================================================================
#define P1_OFF_W    0          // 32*256 u64 = 65536
#define P1_OFF_PART 65536      // 16*32*32 f32 = 65536
#define P1_OFF_X    131072     // 256*33 u64 = 67584
#define P1_OFF_SEQ  198656     // 64*32 int = 8192
#define P1_SMEM     206848

__global__ __launch_bounds__(NTHR, 1)
void embg_kernel(const int* __restrict__ seq,
                 const float* __restrict__ emb_table,
                 const float* __restrict__ W_ih)
{
    extern __shared__ char smem[];
    unsigned long long* w2_sh  = (unsigned long long*)(smem + P1_OFF_W);
    float*              partf  = (float*)(smem + P1_OFF_PART);
    unsigned long long* x_sh   = (unsigned long long*)(smem + P1_OFF_X);
    int*                seq_sh = (int*)(smem + P1_OFF_SEQ);

    const int tid = threadIdx.x;
    const int ks  = tid >> 5;
    const int b   = tid & 31;
    const int rbp = blockIdx.x;
    const int t0  = blockIdx.y * TCHUNK;

    // reset phase-2 generation counter (phase 2 runs after this grid, stream-ordered)
    if (rbp == 0 && blockIdx.y == 0 && tid == 0) g_gen = 0u;

    // stage 32 rows of W_e (K 0..511 as 256 u64 pairs per row)
    for (int idx = tid; idx < 32 * 256; idx += NTHR) {
        int r  = idx >> 8;
        int kp = idx & 255;
        int grow = (r >> 3) * HH + rbp * 8 + (r & 7);
        w2_sh[idx] = ((const unsigned long long*)(W_ih + (size_t)grow * (EE + HH)))[kp];
    }
    for (int i = tid; i < TCHUNK * BB; i += NTHR) {
        int tl = i >> 5, r = i & 31;
        seq_sh[i] = seq[r * SS + t0 + tl];
    }
    __syncthreads();

    // prologue: coalesced embedding stage for tl=0
    #pragma unroll
    for (int i = 0; i < 16; i++) {
        int n  = i * NTHR + tid;
        int r  = n >> 8;
        int kp = n & 255;
        int token = seq_sh[r];
        x_sh[kp * 33 + r] = __ldg(
            (const unsigned long long*)(emb_table + (size_t)token * EE) + kp);
    }
    __syncthreads();

    for (int tl = 0; tl < TCHUNK; tl++) {
        unsigned long long preg[16];
        if (tl + 1 < TCHUNK) {
            #pragma unroll
            for (int i = 0; i < 16; i++) {
                int n  = i * NTHR + tid;
                int r  = n >> 8;
                int kp = n & 255;
                int token = seq_sh[(tl + 1) * BB + r];
                preg[i] = __ldg(
                    (const unsigned long long*)(emb_table + (size_t)token * EE) + kp);
            }
        }

        unsigned long long x[16];
        #pragma unroll
        for (int i = 0; i < 16; i++) x[i] = x_sh[(ks * 16 + i) * 33 + b];

        #pragma unroll
        for (int p = 0; p < 2; p++) {
            unsigned long long acc[16];
            #pragma unroll
            for (int r = 0; r < 16; r++) acc[r] = 0ull;
            #pragma unroll
            for (int i2 = 0; i2 < 8; i2++) {
                unsigned long long xa = x[2 * i2], xb = x[2 * i2 + 1];
                #pragma unroll
                for (int r = 0; r < 16; r++) {
                    ulonglong2 wv = *(const ulonglong2*)
                        (w2_sh + (p * 16 + r) * 256 + ks * 16 + 2 * i2);
                    acc[r] = ffma2u(xa, wv.x, ffma2u(xb, wv.y, acc[r]));
                }
            }
            #pragma unroll
            for (int r = 0; r < 16; r++) {
                F2U a; a.u = acc[r];
                partf[(ks * 32 + p * 16 + r) * BB + b] = a.f.x + a.f.y;
            }
        }
        __syncthreads();

        if (tl + 1 < TCHUNK) {
            #pragma unroll
            for (int i = 0; i < 16; i++) {
                int n  = i * NTHR + tid;
                x_sh[(n & 255) * 33 + (n >> 8)] = preg[i];
            }
        }

        #pragma unroll
        for (int p = 0; p < 2; p++) {
            int rr = p * 16 + ks;
            float s = 0.f;
            #pragma unroll
            for (int kw = 0; kw < 16; kw++) s += partf[(kw * 32 + rr) * BB + b];
            int gate = rr >> 3, jj = rr & 7;
            int bid  = 2 * rbp + (jj >> 2);
            int ko   = gate * 4 + (jj & 3);
            g_embg[((size_t)(t0 + tl) * 128 + bid) * (16 * BB) + ko * BB + b] = s;
        }
        __syncthreads();
    }
}

// ======================================================================
// Phase 2 (R3-measured best): sequential LSTM, recurrent half (K=512).
// 128 CTAs x 512 thr; centralized generation counter, single poller/CTA.
// red.release folds the fence into the publish atomic.
// ======================================================================
#define P2_OFF_W     0         // 16*256 u64 = 32768
#define P2_OFF_PART  32768     // 16*16*32 f32 = 32768
#define P2_OFF_CONST 65536     // 2048
#define P2_OFF_GSUM  67584     // 2048
#define P2_OFF_C0    69632     // 512
#define P2_SMEM      70400

__global__ __launch_bounds__(NTHR, 1)
void lstm_seq_kernel(const float* __restrict__ enc_h,
                     const float* __restrict__ enc_c,
                     const float* __restrict__ W_ih,
                     const float* __restrict__ W_hh,
                     const float* __restrict__ b_ih,
                     const float* __restrict__ b_hh,
                     float* __restrict__ out)
{
    extern __shared__ char smem[];
    unsigned long long* w2_sh = (unsigned long long*)(smem + P2_OFF_W);
    float*              partf = (float*)(smem + P2_OFF_PART);
    float*              cns_sh = (float*)(smem + P2_OFF_CONST);
    float*              gsum   = (float*)(smem + P2_OFF_GSUM);
    float*              c0_sh  = (float*)(smem + P2_OFF_C0);

    const int tid = threadIdx.x;
    const int bid = blockIdx.x;
    const int ks  = tid >> 5;
    const int b   = tid & 31;
    const int j0  = bid * JPB;

    for (int idx = tid; idx < 16 * 256; idx += NTHR) {
        int r  = idx >> 8;
        int kp = idx & 255;
        int grow = (r >> 2) * HH + j0 + (r & 3);
        w2_sh[idx] = ((const unsigned long long*)(W_ih + (size_t)grow * (EE + HH)))[256 + kp];
    }
    if (tid < 128) c0_sh[ks * BB + b] = enc_c[b * HH + j0 + ks];
    __syncthreads();

    // const = h0 @ W_hh^T + b_ih + b_hh
    {
        float h0c[32];
        #pragma unroll
        for (int i = 0; i < 32; i++) h0c[i] = enc_h[b * HH + ks * 32 + i];
        #pragma unroll
        for (int r = 0; r < 16; r++) {
            const float* wr = W_hh + (size_t)((r >> 2) * HH + j0 + (r & 3)) * HH + ks * 32;
            float acc = 0.f;
            #pragma unroll
            for (int i = 0; i < 32; i++) acc = fmaf(h0c[i], wr[i], acc);
            partf[(ks * 16 + r) * BB + b] = acc;
        }
        __syncthreads();
        {
            float s = 0.f;
            #pragma unroll
            for (int k2 = 0; k2 < 16; k2++) s += partf[(k2 * 16 + ks) * BB + b];
            int grow = (ks >> 2) * HH + j0 + (ks & 3);
            cns_sh[ks * BB + b] = s + b_ih[grow] + b_hh[grow];
        }
        __syncthreads();
    }

    for (int t = 0; t < SS; t++) {
        // emb-gate contribution: independent of h, issue first
        float embv = __ldcg(&g_embg[((size_t)t * 128 + bid) * (16 * BB) + ks * BB + b]);

        unsigned long long x[16];
        if (t > 0) {
            if (tid == 0) {
                unsigned target = 128u * (unsigned)t;
                while (ld_acq(&g_gen) < target) { }
            }
            __syncthreads();
            const unsigned long long* hb = &g_ht2[(t - 1) & 1][ks * 16][0];
            #pragma unroll
            for (int i = 0; i < 16; i++) x[i] = __ldcg(&hb[i * BB + b]);
        } else {
            #pragma unroll
            for (int i = 0; i < 16; i++) x[i] = 0ull;
        }

        unsigned long long acc[16];
        #pragma unroll
        for (int r = 0; r < 16; r++) acc[r] = 0ull;
        #pragma unroll
        for (int i2 = 0; i2 < 8; i2++) {
            unsigned long long xa = x[2 * i2], xb = x[2 * i2 + 1];
            #pragma unroll
            for (int r = 0; r < 16; r++) {
                ulonglong2 wv = *(const ulonglong2*)(w2_sh + r * 256 + ks * 16 + 2 * i2);
                acc[r] = ffma2u(xa, wv.x, ffma2u(xb, wv.y, acc[r]));
            }
        }
        #pragma unroll
        for (int r = 0; r < 16; r++) {
            F2U a; a.u = acc[r];
            partf[(ks * 16 + r) * BB + b] = a.f.x + a.f.y;
        }
        __syncthreads();   // sync#1: partf ready

        {
            float s = 0.f;
            #pragma unroll
            for (int k2 = 0; k2 < 16; k2++) s += partf[(k2 * 16 + ks) * BB + b];
            gsum[ks * BB + b] = s + cns_sh[ks * BB + b] + embv;
        }
        __syncthreads();   // sync#2: gsum ready

        if (tid < 128) {
            int jj = ks;
            float iv = gsum[(0 * 4 + jj) * BB + b];
            float fv = gsum[(1 * 4 + jj) * BB + b];
            float gv = gsum[(2 * 4 + jj) * BB + b];
            float ov = gsum[(3 * 4 + jj) * BB + b];
            float ig = sigmoidf_(iv);
            float fg = sigmoidf_(fv);
            float gg = tanhf(gv);
            float og = sigmoidf_(ov);
            float cc = fg * c0_sh[jj * BB + b] + ig * gg;
            float hh = og * tanhf(cc);
            // h scratch first (critical path), out[] after
            float* hp = (float*)&g_ht2[t & 1][2 * bid + (jj >> 1)][b];
            hp[jj & 1] = hh;
            out[(size_t)b * (SS * HH) + (size_t)t * HH + j0 + jj] = hh;
        }
        __syncthreads();   // sync#3: h stores complete before publish

        if (tid == 0) red_release_add(&g_gen, 1u);
    }
}

extern "C" void kernel_launch(void* const* d_in, const int* in_sizes, int n_in,
                              void* d_out, int out_size) {
    const int*   seq   = (const int*)d_in[0];
    // d_in[1] = enc_out : unused
    const float* enc_h = (const float*)d_in[2];
    const float* enc_c = (const float*)d_in[3];
    const float* emb   = (const float*)d_in[4];
    const float* W_ih  = (const float*)d_in[5];
    const float* W_hh  = (const float*)d_in[6];
    const float* b_ih  = (const float*)d_in[7];
    const float* b_hh  = (const float*)d_in[8];
    float* out = (float*)d_out;

    static bool attr_set = false;
    if (!attr_set) {
        cudaFuncSetAttribute(embg_kernel,
                             cudaFuncAttributeMaxDynamicSharedMemorySize, P1_SMEM);
        cudaFuncSetAttribute(lstm_seq_kernel,
                             cudaFuncAttributeMaxDynamicSharedMemorySize, P2_SMEM);
        attr_set = true;
    }

    dim3 g1(64, SS / TCHUNK);
    embg_kernel<<<g1, NTHR, P1_SMEM>>>(seq, emb, W_ih);
    lstm_seq_kernel<<<128, NTHR, P2_SMEM>>>(enc_h, enc_c, W_ih, W_hh,
                                            b_ih, b_hh, out);
}

// round 12
// speedup vs baseline: 1.7486x; 1.0158x over previous
#include <cuda_runtime.h>
#include <math.h>

#define BB   32
#define SS   512
#define HH   512
#define EE   512
#define JPB  4
#define NTHR 512
#define TCHUNK 64

// ---------- global scratch ----------
__device__ float g_embg[(size_t)SS * 128 * 16 * BB];   // [t][bid(128)][r(16)][b(32)]
__device__ unsigned long long g_ht2[2][256][BB];        // [buf][jpair][b]
__device__ unsigned g_gen;

union F2U { unsigned long long u; float2 f; };

__device__ __forceinline__ unsigned long long ffma2u(unsigned long long a,
                                                     unsigned long long b,
                                                     unsigned long long c) {
    unsigned long long d;
    asm("fma.rn.f32x2 %0, %1, %2, %3;" : "=l"(d) : "l"(a), "l"(b), "l"(c));
    return d;
}

__device__ __forceinline__ unsigned ld_acq(const unsigned* p) {
    unsigned v;
    asm volatile("ld.global.acquire.gpu.u32 %0, [%1];" : "=r"(v) : "l"(p) : "memory");
    return v;
}
__device__ __forceinline__ void red_release_add(unsigned* p, unsigned v) {
    asm volatile("red.release.gpu.global.add.u32 [%0], %1;" :: "l"(p), "r"(v) : "memory");
}

__device__ __forceinline__ float fast_sigmoid(float x) {
    return __fdividef(1.0f, 1.0f + __expf(-x));
}
__device__ __forceinline__ float fast_tanh(float x) {
    return __fdividef(2.0f, 1.0f + __expf(-2.0f * x)) - 1.0f;
}

// ======================================================================
// Phase 1 (unchanged, R8/R11-measured): emb_gates, 32 rows/CTA, coalesced
// smem-staged embeddings. grid (64 rowpairs, 8 tchunks) x 512. Resets g_gen.
// ======================================================================
#define P1_OFF_W    0          // 32*256 u64 = 65536
#define P1_OFF_PART 65536      // 16*32*32 f32 = 65536
#define P1_OFF_X    131072     // 256*33 u64 = 67584
#define P1_OFF_SEQ  198656     // 64*32 int = 8192
#define P1_SMEM     206848

__global__ __launch_bounds__(NTHR, 1)
void embg_kernel(const int* __restrict__ seq,
                 const float* __restrict__ emb_table,
                 const float* __restrict__ W_ih)
{
    extern __shared__ char smem[];
    unsigned long long* w2_sh  = (unsigned long long*)(smem + P1_OFF_W);
    float*              partf  = (float*)(smem + P1_OFF_PART);
    unsigned long long* x_sh   = (unsigned long long*)(smem + P1_OFF_X);
    int*                seq_sh = (int*)(smem + P1_OFF_SEQ);

    const int tid = threadIdx.x;
    const int ks  = tid >> 5;
    const int b   = tid & 31;
    const int rbp = blockIdx.x;
    const int t0  = blockIdx.y * TCHUNK;

    if (rbp == 0 && blockIdx.y == 0 && tid == 0) g_gen = 0u;

    for (int idx = tid; idx < 32 * 256; idx += NTHR) {
        int r  = idx >> 8;
        int kp = idx & 255;
        int grow = (r >> 3) * HH + rbp * 8 + (r & 7);
        w2_sh[idx] = ((const unsigned long long*)(W_ih + (size_t)grow * (EE + HH)))[kp];
    }
    for (int i = tid; i < TCHUNK * BB; i += NTHR) {
        int tl = i >> 5, r = i & 31;
        seq_sh[i] = seq[r * SS + t0 + tl];
    }
    __syncthreads();

    #pragma unroll
    for (int i = 0; i < 16; i++) {
        int n  = i * NTHR + tid;
        int r  = n >> 8;
        int kp = n & 255;
        int token = seq_sh[r];
        x_sh[kp * 33 + r] = __ldg(
            (const unsigned long long*)(emb_table + (size_t)token * EE) + kp);
    }
    __syncthreads();

    for (int tl = 0; tl < TCHUNK; tl++) {
        unsigned long long preg[16];
        if (tl + 1 < TCHUNK) {
            #pragma unroll
            for (int i = 0; i < 16; i++) {
                int n  = i * NTHR + tid;
                int r  = n >> 8;
                int kp = n & 255;
                int token = seq_sh[(tl + 1) * BB + r];
                preg[i] = __ldg(
                    (const unsigned long long*)(emb_table + (size_t)token * EE) + kp);
            }
        }

        unsigned long long x[16];
        #pragma unroll
        for (int i = 0; i < 16; i++) x[i] = x_sh[(ks * 16 + i) * 33 + b];

        #pragma unroll
        for (int p = 0; p < 2; p++) {
            unsigned long long acc[16];
            #pragma unroll
            for (int r = 0; r < 16; r++) acc[r] = 0ull;
            #pragma unroll
            for (int i2 = 0; i2 < 8; i2++) {
                unsigned long long xa = x[2 * i2], xb = x[2 * i2 + 1];
                #pragma unroll
                for (int r = 0; r < 16; r++) {
                    ulonglong2 wv = *(const ulonglong2*)
                        (w2_sh + (p * 16 + r) * 256 + ks * 16 + 2 * i2);
                    acc[r] = ffma2u(xa, wv.x, ffma2u(xb, wv.y, acc[r]));
                }
            }
            #pragma unroll
            for (int r = 0; r < 16; r++) {
                F2U a; a.u = acc[r];
                partf[(ks * 32 + p * 16 + r) * BB + b] = a.f.x + a.f.y;
            }
        }
        __syncthreads();

        if (tl + 1 < TCHUNK) {
            #pragma unroll
            for (int i = 0; i < 16; i++) {
                int n  = i * NTHR + tid;
                x_sh[(n & 255) * 33 + (n >> 8)] = preg[i];
            }
        }

        #pragma unroll
        for (int p = 0; p < 2; p++) {
            int rr = p * 16 + ks;
            float s = 0.f;
            #pragma unroll
            for (int kw = 0; kw < 16; kw++) s += partf[(kw * 32 + rr) * BB + b];
            int gate = rr >> 3, jj = rr & 7;
            int bid  = 2 * rbp + (jj >> 2);
            int ko   = gate * 4 + (jj & 3);
            g_embg[((size_t)(t0 + tl) * 128 + bid) * (16 * BB) + ko * BB + b] = s;
        }
        __syncthreads();
    }
}

// ======================================================================
// Phase 2 (v12): 128 CTAs x 512 thr. Double-buffered partf, merged
// reduce+nonlin on warps 12-15 (hi-wid arbiter priority), 2 full bars +
// 1 named bar per step, fast-math nonlin, embv prefetch.
// partf layout: [buf][r(16)][ks(16)][b(32)] f32
// ======================================================================
#define P2_OFF_W     0         // 16*256 u64 = 32768
#define P2_OFF_PART  32768     // 2*16*16*32 f32 = 65536
#define P2_OFF_CNS   98304     // 16*32 f32 = 2048
#define P2_OFF_C0    100352    // 4*32 f32 = 512
#define P2_SMEM      100992

__global__ __launch_bounds__(NTHR, 1)
void lstm_seq_kernel(const float* __restrict__ enc_h,
                     const float* __restrict__ enc_c,
                     const float* __restrict__ W_ih,
                     const float* __restrict__ W_hh,
                     const float* __restrict__ b_ih,
                     const float* __restrict__ b_hh,
                     float* __restrict__ out)
{
    extern __shared__ char smem[];
    unsigned long long* w2_sh = (unsigned long long*)(smem + P2_OFF_W);
    float*              partf = (float*)(smem + P2_OFF_PART);
    float*              cns_sh = (float*)(smem + P2_OFF_CNS);
    float*              c0_sh  = (float*)(smem + P2_OFF_C0);

    const int tid = threadIdx.x;
    const int bid = blockIdx.x;
    const int ks  = tid >> 5;
    const int b   = tid & 31;
    const int j0  = bid * JPB;

    for (int idx = tid; idx < 16 * 256; idx += NTHR) {
        int r  = idx >> 8;
        int kp = idx & 255;
        int grow = (r >> 2) * HH + j0 + (r & 3);
        w2_sh[idx] = ((const unsigned long long*)(W_ih + (size_t)grow * (EE + HH)))[256 + kp];
    }
    if (tid < 128) c0_sh[(tid >> 5) * BB + b] = enc_c[b * HH + j0 + (tid >> 5)];
    __syncthreads();

    // const = h0 @ W_hh^T + b_ih + b_hh  (use partf buf0 as scratch)
    {
        float h0c[32];
        #pragma unroll
        for (int i = 0; i < 32; i++) h0c[i] = enc_h[b * HH + ks * 32 + i];
        #pragma unroll
        for (int r = 0; r < 16; r++) {
            const float* wr = W_hh + (size_t)((r >> 2) * HH + j0 + (r & 3)) * HH + ks * 32;
            float acc = 0.f;
            #pragma unroll
            for (int i = 0; i < 32; i++) acc = fmaf(h0c[i], wr[i], acc);
            partf[r * 512 + ks * 32 + b] = acc;
        }
        __syncthreads();
        {
            float s = 0.f;
            #pragma unroll
            for (int k2 = 0; k2 < 16; k2++) s += partf[ks * 512 + k2 * 32 + b];
            int grow = (ks >> 2) * HH + j0 + (ks & 3);
            cns_sh[ks * BB + b] = s + b_ih[grow] + b_hh[grow];
        }
        __syncthreads();
    }

    // reducer identity (warps 12-15): u = tid-384, jj = u>>5, bb = u&31
    const bool is_red = (tid >= 384);
    const int  u  = tid - 384;
    const int  jj = u >> 5;
    const int  bb = u & 31;

    // prefetch embv for t=0 (rows jj, 4+jj, 8+jj, 12+jj)
    float embv[4];
    if (is_red) {
        #pragma unroll
        for (int g = 0; g < 4; g++)
            embv[g] = __ldcg(&g_embg[(size_t)bid * (16 * BB) + (g * 4 + jj) * BB + bb]);
    }

    for (int t = 0; t < SS; t++) {
        unsigned long long x[16];
        if (t > 0) {
            if (tid == 511) {
                unsigned target = 128u * (unsigned)t;
                while (ld_acq(&g_gen) < target) { }
            }
            __syncthreads();   // BAR A: h(t-1) globally visible
            const unsigned long long* hb = &g_ht2[(t - 1) & 1][ks * 16][0];
            #pragma unroll
            for (int i = 0; i < 16; i++) x[i] = __ldcg(&hb[i * BB + b]);
        } else {
            #pragma unroll
            for (int i = 0; i < 16; i++) x[i] = 0ull;
        }

        float* pf = partf + (t & 1) * 8192;

        unsigned long long acc[16];
        #pragma unroll
        for (int r = 0; r < 16; r++) acc[r] = 0ull;
        #pragma unroll
        for (int i2 = 0; i2 < 8; i2++) {
            unsigned long long xa = x[2 * i2], xb = x[2 * i2 + 1];
            #pragma unroll
            for (int r = 0; r < 16; r++) {
                ulonglong2 wv = *(const ulonglong2*)(w2_sh + r * 256 + ks * 16 + 2 * i2);
                acc[r] = ffma2u(xa, wv.x, ffma2u(xb, wv.y, acc[r]));
            }
        }
        #pragma unroll
        for (int r = 0; r < 16; r++) {
            F2U a; a.u = acc[r];
            pf[r * 512 + ks * 32 + b] = a.f.x + a.f.y;
        }
        __syncthreads();   // BAR B: partf[t&1] complete

        if (is_red) {
            // merged reduce + nonlin for h[j0+jj], batch bb
            float gs[4];
            #pragma unroll
            for (int g = 0; g < 4; g++) {
                int r = g * 4 + jj;
                float s = 0.f;
                #pragma unroll
                for (int k2 = 0; k2 < 16; k2++) s += pf[r * 512 + k2 * 32 + bb];
                gs[g] = s + cns_sh[r * BB + bb] + embv[g];
            }
            float ig = fast_sigmoid(gs[0]);
            float fg = fast_sigmoid(gs[1]);
            float gg = fast_tanh(gs[2]);
            float og = fast_sigmoid(gs[3]);
            float cc = fg * c0_sh[jj * BB + bb] + ig * gg;
            float hh = og * fast_tanh(cc);

            float* hp = (float*)&g_ht2[t & 1][2 * bid + (jj >> 1)][bb];
            hp[jj & 1] = hh;

            asm volatile("bar.sync 1, 128;" ::: "memory");   // reducers' h stores done
            if (tid == 511) red_release_add(&g_gen, 1u);

            // off critical path: output store + next-step embv prefetch
            out[(size_t)bb * (SS * HH) + (size_t)t * HH + j0 + jj] = hh;
            if (t + 1 < SS) {
                #pragma unroll
                for (int g = 0; g < 4; g++)
                    embv[g] = __ldcg(&g_embg[((size_t)(t + 1) * 128 + bid) * (16 * BB)
                                             + (g * 4 + jj) * BB + bb]);
            }
        }
        // no further barrier: partf[t&1] is next written at t+2, and BAR A(t+2)
        // cannot release before the reducers (these same threads) arrive there,
        // which is after this reduce completed.
    }
}

extern "C" void kernel_launch(void* const* d_in, const int* in_sizes, int n_in,
                              void* d_out, int out_size) {
    const int*   seq   = (const int*)d_in[0];
    // d_in[1] = enc_out : unused
    const float* enc_h = (const float*)d_in[2];
    const float* enc_c = (const float*)d_in[3];
    const float* emb   = (const float*)d_in[4];
    const float* W_ih  = (const float*)d_in[5];
    const float* W_hh  = (const float*)d_in[6];
    const float* b_ih  = (const float*)d_in[7];
    const float* b_hh  = (const float*)d_in[8];
    float* out = (float*)d_out;

    static bool attr_set = false;
    if (!attr_set) {
        cudaFuncSetAttribute(embg_kernel,
                             cudaFuncAttributeMaxDynamicSharedMemorySize, P1_SMEM);
        cudaFuncSetAttribute(lstm_seq_kernel,
                             cudaFuncAttributeMaxDynamicSharedMemorySize, P2_SMEM);
        attr_set = true;
    }

    dim3 g1(64, SS / TCHUNK);
    embg_kernel<<<g1, NTHR, P1_SMEM>>>(seq, emb, W_ih);
    lstm_seq_kernel<<<128, NTHR, P2_SMEM>>>(enc_h, enc_c, W_ih, W_hh,
                                            b_ih, b_hh, out);
}

// round 13
// speedup vs baseline: 2.0312x; 1.1616x over previous
#include <cuda_runtime.h>
#include <math.h>

#define BB   32
#define SS   512
#define HH   512
#define EE   512
#define JPB  4
#define NTHR 512

// ---------- global scratch ----------
__device__ unsigned long long g_ht2[2][256][BB];   // [buf][jpair][b]
__device__ unsigned g_gen;

union F2U { unsigned long long u; float2 f; };

__device__ __forceinline__ unsigned long long ffma2u(unsigned long long a,
                                                     unsigned long long b,
                                                     unsigned long long c) {
    unsigned long long d;
    asm("fma.rn.f32x2 %0, %1, %2, %3;" : "=l"(d) : "l"(a), "l"(b), "l"(c));
    return d;
}

__device__ __forceinline__ unsigned ld_acq(const unsigned* p) {
    unsigned v;
    asm volatile("ld.global.acquire.gpu.u32 %0, [%1];" : "=r"(v) : "l"(p) : "memory");
    return v;
}
__device__ __forceinline__ void red_release_add(unsigned* p, unsigned v) {
    asm volatile("red.release.gpu.global.add.u32 [%0], %1;" :: "l"(p), "r"(v) : "memory");
}

__device__ __forceinline__ float fast_sigmoid(float x) {
    return __fdividef(1.0f, 1.0f + __expf(-x));
}
__device__ __forceinline__ float fast_tanh(float x) {
    return __fdividef(2.0f, 1.0f + __expf(-2.0f * x)) - 1.0f;
}

__global__ void reset_gen_kernel() { g_gen = 0u; }

// ======================================================================
// Fused persistent LSTM: 128 CTAs x 512 threads, 1/SM.
// CTA bid owns h[j0..j0+3] (16 gate rows). Per step:
//   BAR A (h ready) -> STS x_emb(t+1 tokens, from preg) -> gather h ->
//   rec-FMA (accumulates onto emb partials left in acc by prev step) ->
//   STS partf -> BAR B -> reducers: reduce+nonlin+publish (overlapped
//   with other warps' emb-FMA for t+1) -> emb-FMA(t+1) -> preg LDG(t+2).
// smem: W_ih full rows (emb half kp 0..255, rec half 256..511).
// ======================================================================
#define OFF_W    0          // 16*512 u64 = 65536
#define OFF_PART 65536      // 16*512 f32 = 32768
#define OFF_X    98304      // 256*33 u64 = 67584 (padded for bank-free transpose)
#define OFF_CNS  165888     // 16*32 f32 = 2048
#define OFF_C0   167936     // 4*32 f32 = 512
#define SMEM_TOT 168448

__global__ __launch_bounds__(NTHR, 1)
void lstm_fused_kernel(const int* __restrict__ seq,
                       const float* __restrict__ enc_h,
                       const float* __restrict__ enc_c,
                       const float* __restrict__ emb_table,
                       const float* __restrict__ W_ih,
                       const float* __restrict__ W_hh,
                       const float* __restrict__ b_ih,
                       const float* __restrict__ b_hh,
                       float* __restrict__ out)
{
    extern __shared__ char smem[];
    unsigned long long* w2_sh  = (unsigned long long*)(smem + OFF_W);
    float*              partf  = (float*)(smem + OFF_PART);
    unsigned long long* x_sh   = (unsigned long long*)(smem + OFF_X);
    float*              cns_sh = (float*)(smem + OFF_CNS);
    float*              c0_sh  = (float*)(smem + OFF_C0);

    const int tid = threadIdx.x;
    const int bid = blockIdx.x;
    const int ks  = tid >> 5;
    const int b   = tid & 31;
    const int j0  = bid * JPB;

    // ---- stage FULL W_ih rows (emb pairs 0..255, rec pairs 256..511) ----
    for (int idx = tid; idx < 16 * 512; idx += NTHR) {
        int r  = idx >> 9;
        int kp = idx & 511;
        int grow = (r >> 2) * HH + j0 + (r & 3);
        w2_sh[idx] = ((const unsigned long long*)(W_ih + (size_t)grow * (EE + HH)))[kp];
    }
    if (tid < 128) c0_sh[(tid >> 5) * BB + b] = enc_c[b * HH + j0 + (tid >> 5)];
    __syncthreads();

    // ---- const = h0 @ W_hh^T + b_ih + b_hh (partf as scratch) ----
    {
        float h0c[32];
        #pragma unroll
        for (int i = 0; i < 32; i++) h0c[i] = enc_h[b * HH + ks * 32 + i];
        #pragma unroll
        for (int r = 0; r < 16; r++) {
            const float* wr = W_hh + (size_t)((r >> 2) * HH + j0 + (r & 3)) * HH + ks * 32;
            float acc = 0.f;
            #pragma unroll
            for (int i = 0; i < 32; i++) acc = fmaf(h0c[i], wr[i], acc);
            partf[r * 512 + ks * 32 + b] = acc;
        }
        __syncthreads();
        {
            float s = 0.f;
            #pragma unroll
            for (int k2 = 0; k2 < 16; k2++) s += partf[ks * 512 + k2 * 32 + b];
            int grow = (ks >> 2) * HH + j0 + (ks & 3);
            cns_sh[ks * BB + b] = s + b_ih[grow] + b_hh[grow];
        }
        __syncthreads();
    }

    // ---- prologue: stage x_emb for t=0, emb-FMA(0) -> acc, preg <- t=1 ----
    unsigned long long preg[16];
    {
        #pragma unroll
        for (int i = 0; i < 16; i++) {
            int n  = i * NTHR + tid;
            int r32 = n >> 8;
            int kp  = n & 255;
            int token = __ldg(&seq[r32 * SS + 0]);
            preg[i] = __ldg((const unsigned long long*)
                            (emb_table + (size_t)token * EE) + kp);
        }
        #pragma unroll
        for (int i = 0; i < 16; i++) {
            int n = i * NTHR + tid;
            x_sh[(n & 255) * 33 + (n >> 8)] = preg[i];
        }
        __syncthreads();
    }

    unsigned long long acc[16];
    {
        unsigned long long x[16];
        #pragma unroll
        for (int i = 0; i < 16; i++) x[i] = x_sh[(ks * 16 + i) * 33 + b];
        #pragma unroll
        for (int r = 0; r < 16; r++) acc[r] = 0ull;
        #pragma unroll
        for (int i2 = 0; i2 < 8; i2++) {
            unsigned long long xa = x[2 * i2], xb = x[2 * i2 + 1];
            #pragma unroll
            for (int r = 0; r < 16; r++) {
                ulonglong2 wv = *(const ulonglong2*)(w2_sh + r * 512 + ks * 16 + 2 * i2);
                acc[r] = ffma2u(xa, wv.x, ffma2u(xb, wv.y, acc[r]));
            }
        }
        // preg <- embeddings of tokens at t=1
        #pragma unroll
        for (int i = 0; i < 16; i++) {
            int n  = i * NTHR + tid;
            int r32 = n >> 8;
            int kp  = n & 255;
            int token = __ldg(&seq[r32 * SS + 1]);
            preg[i] = __ldg((const unsigned long long*)
                            (emb_table + (size_t)token * EE) + kp);
        }
    }

    const bool is_red = (tid >= 384);
    const int  u  = tid - 384;
    const int  jj = u >> 5;
    const int  bb = u & 31;

    for (int t = 0; t < SS; t++) {
        if (t > 0) {
            if (tid == 511) {
                unsigned target = 128u * (unsigned)t;
                while (ld_acq(&g_gen) < target) { }
            }
            __syncthreads();   // BAR A: h(t-1) globally visible
        }

        // stage x_emb with tokens for step t+1 (reads of step-t data finished
        // before BAR A by every thread's emb-FMA last iteration)
        if (t + 1 < SS) {
            #pragma unroll
            for (int i = 0; i < 16; i++) {
                int n = i * NTHR + tid;
                x_sh[(n & 255) * 33 + (n >> 8)] = preg[i];
            }
        }

        // recurrent half accumulates onto emb partials already in acc
        if (t > 0) {
            unsigned long long x[16];
            const unsigned long long* hb = &g_ht2[(t - 1) & 1][ks * 16][0];
            #pragma unroll
            for (int i = 0; i < 16; i++) x[i] = __ldcg(&hb[i * BB + b]);
            #pragma unroll
            for (int i2 = 0; i2 < 8; i2++) {
                unsigned long long xa = x[2 * i2], xb = x[2 * i2 + 1];
                #pragma unroll
                for (int r = 0; r < 16; r++) {
                    ulonglong2 wv = *(const ulonglong2*)
                        (w2_sh + r * 512 + 256 + ks * 16 + 2 * i2);
                    acc[r] = ffma2u(xa, wv.x, ffma2u(xb, wv.y, acc[r]));
                }
            }
        }
        #pragma unroll
        for (int r = 0; r < 16; r++) {
            F2U a; a.u = acc[r];
            partf[r * 512 + ks * 32 + b] = a.f.x + a.f.y;
        }
        __syncthreads();   // BAR B: partf + x_emb staged

        if (is_red) {
            float gs[4];
            #pragma unroll
            for (int g = 0; g < 4; g++) {
                int r = g * 4 + jj;
                float s = 0.f;
                #pragma unroll
                for (int k2 = 0; k2 < 16; k2++) s += partf[r * 512 + k2 * 32 + bb];
                gs[g] = s + cns_sh[r * BB + bb];
            }
            float ig = fast_sigmoid(gs[0]);
            float fg = fast_sigmoid(gs[1]);
            float gg = fast_tanh(gs[2]);
            float og = fast_sigmoid(gs[3]);
            float cc = fg * c0_sh[jj * BB + bb] + ig * gg;
            float hh = og * fast_tanh(cc);

            float* hp = (float*)&g_ht2[t & 1][2 * bid + (jj >> 1)][bb];
            hp[jj & 1] = hh;
            asm volatile("bar.sync 1, 128;" ::: "memory");
            if (tid == 511) red_release_add(&g_gen, 1u);
            out[(size_t)bb * (SS * HH) + (size_t)t * HH + j0 + jj] = hh;
        }

        // emb-FMA for step t+1 (overlaps reducers' reduce/publish)
        if (t + 1 < SS) {
            unsigned long long x[16];
            #pragma unroll
            for (int i = 0; i < 16; i++) x[i] = x_sh[(ks * 16 + i) * 33 + b];
            #pragma unroll
            for (int r = 0; r < 16; r++) acc[r] = 0ull;
            #pragma unroll
            for (int i2 = 0; i2 < 8; i2++) {
                unsigned long long xa = x[2 * i2], xb = x[2 * i2 + 1];
                #pragma unroll
                for (int r = 0; r < 16; r++) {
                    ulonglong2 wv = *(const ulonglong2*)
                        (w2_sh + r * 512 + ks * 16 + 2 * i2);
                    acc[r] = ffma2u(xa, wv.x, ffma2u(xb, wv.y, acc[r]));
                }
            }
            if (t + 2 < SS) {
                #pragma unroll
                for (int i = 0; i < 16; i++) {
                    int n  = i * NTHR + tid;
                    int r32 = n >> 8;
                    int kp  = n & 255;
                    int token = __ldg(&seq[r32 * SS + t + 2]);
                    preg[i] = __ldg((const unsigned long long*)
                                    (emb_table + (size_t)token * EE) + kp);
                }
            }
        }
        // partf single-buffer safe: next write is after BAR A(t+1), which the
        // reducers (who read partf) must reach first.
    }
}

extern "C" void kernel_launch(void* const* d_in, const int* in_sizes, int n_in,
                              void* d_out, int out_size) {
    const int*   seq   = (const int*)d_in[0];
    // d_in[1] = enc_out : unused
    const float* enc_h = (const float*)d_in[2];
    const float* enc_c = (const float*)d_in[3];
    const float* emb   = (const float*)d_in[4];
    const float* W_ih  = (const float*)d_in[5];
    const float* W_hh  = (const float*)d_in[6];
    const float* b_ih  = (const float*)d_in[7];
    const float* b_hh  = (const float*)d_in[8];
    float* out = (float*)d_out;

    static bool attr_set = false;
    if (!attr_set) {
        cudaFuncSetAttribute(lstm_fused_kernel,
                             cudaFuncAttributeMaxDynamicSharedMemorySize, SMEM_TOT);
        attr_set = true;
    }

    reset_gen_kernel<<<1, 1>>>();
    lstm_fused_kernel<<<128, NTHR, SMEM_TOT>>>(seq, enc_h, enc_c, emb,
                                               W_ih, W_hh, b_ih, b_hh, out);
}

// round 14
// speedup vs baseline: 2.0658x; 1.0170x over previous
#include <cuda_runtime.h>
#include <math.h>

#define BB   32
#define SS   512
#define HH   512
#define EE   512
#define JPB  4
#define NTHR 512

// ---------- global scratch ----------
__device__ unsigned long long g_ht2[2][256][BB];   // [buf][jpair][b]
__device__ unsigned g_gen16[16];                    // hierarchical step counters

union F2U { unsigned long long u; float2 f; };

__device__ __forceinline__ unsigned long long ffma2u(unsigned long long a,
                                                     unsigned long long b,
                                                     unsigned long long c) {
    unsigned long long d;
    asm("fma.rn.f32x2 %0, %1, %2, %3;" : "=l"(d) : "l"(a), "l"(b), "l"(c));
    return d;
}

__device__ __forceinline__ unsigned ld_acq(const unsigned* p) {
    unsigned v;
    asm volatile("ld.global.acquire.gpu.u32 %0, [%1];" : "=r"(v) : "l"(p) : "memory");
    return v;
}
__device__ __forceinline__ void red_release_add(unsigned* p, unsigned v) {
    asm volatile("red.release.gpu.global.add.u32 [%0], %1;" :: "l"(p), "r"(v) : "memory");
}

__device__ __forceinline__ float fast_sigmoid(float x) {
    return __fdividef(1.0f, 1.0f + __expf(-x));
}
__device__ __forceinline__ float fast_tanh(float x) {
    return __fdividef(2.0f, 1.0f + __expf(-2.0f * x)) - 1.0f;
}

__global__ void reset_gen_kernel() {
    if (threadIdx.x < 16) g_gen16[threadIdx.x] = 0u;
}

// ======================================================================
// Fused persistent LSTM (R13 structure + hierarchical counters):
// 128 CTAs x 512 threads, 1/SM. CTA bid owns h[j0..j0+3] (16 gate rows).
// Publish: red.release to g_gen16[bid&15] (8 CTAs/counter -> ~216cyc
// serialization instead of ~3.5K on a single counter).
// Wait: threads 0..15 acquire-poll counter tid for >= 8t; syncthreads ANDs.
// ======================================================================
#define OFF_W    0          // 16*512 u64 = 65536
#define OFF_PART 65536      // 16*512 f32 = 32768
#define OFF_X    98304      // 256*33 u64 = 67584 (padded)
#define OFF_CNS  165888     // 16*32 f32 = 2048
#define OFF_C0   167936     // 4*32 f32 = 512
#define SMEM_TOT 168448

__global__ __launch_bounds__(NTHR, 1)
void lstm_fused_kernel(const int* __restrict__ seq,
                       const float* __restrict__ enc_h,
                       const float* __restrict__ enc_c,
                       const float* __restrict__ emb_table,
                       const float* __restrict__ W_ih,
                       const float* __restrict__ W_hh,
                       const float* __restrict__ b_ih,
                       const float* __restrict__ b_hh,
                       float* __restrict__ out)
{
    extern __shared__ char smem[];
    unsigned long long* w2_sh  = (unsigned long long*)(smem + OFF_W);
    float*              partf  = (float*)(smem + OFF_PART);
    unsigned long long* x_sh   = (unsigned long long*)(smem + OFF_X);
    float*              cns_sh = (float*)(smem + OFF_CNS);
    float*              c0_sh  = (float*)(smem + OFF_C0);

    const int tid = threadIdx.x;
    const int bid = blockIdx.x;
    const int ks  = tid >> 5;
    const int b   = tid & 31;
    const int j0  = bid * JPB;

    // ---- stage FULL W_ih rows (emb pairs 0..255, rec pairs 256..511) ----
    for (int idx = tid; idx < 16 * 512; idx += NTHR) {
        int r  = idx >> 9;
        int kp = idx & 511;
        int grow = (r >> 2) * HH + j0 + (r & 3);
        w2_sh[idx] = ((const unsigned long long*)(W_ih + (size_t)grow * (EE + HH)))[kp];
    }
    if (tid < 128) c0_sh[(tid >> 5) * BB + b] = enc_c[b * HH + j0 + (tid >> 5)];
    __syncthreads();

    // ---- const = h0 @ W_hh^T + b_ih + b_hh (partf as scratch) ----
    {
        float h0c[32];
        #pragma unroll
        for (int i = 0; i < 32; i++) h0c[i] = enc_h[b * HH + ks * 32 + i];
        #pragma unroll
        for (int r = 0; r < 16; r++) {
            const float* wr = W_hh + (size_t)((r >> 2) * HH + j0 + (r & 3)) * HH + ks * 32;
            float acc = 0.f;
            #pragma unroll
            for (int i = 0; i < 32; i++) acc = fmaf(h0c[i], wr[i], acc);
            partf[r * 512 + ks * 32 + b] = acc;
        }
        __syncthreads();
        {
            float s = 0.f;
            #pragma unroll
            for (int k2 = 0; k2 < 16; k2++) s += partf[ks * 512 + k2 * 32 + b];
            int grow = (ks >> 2) * HH + j0 + (ks & 3);
            cns_sh[ks * BB + b] = s + b_ih[grow] + b_hh[grow];
        }
        __syncthreads();
    }

    // ---- prologue: stage x_emb for t=0, emb-FMA(0) -> acc, preg <- t=1 ----
    unsigned long long preg[16];
    {
        #pragma unroll
        for (int i = 0; i < 16; i++) {
            int n  = i * NTHR + tid;
            int r32 = n >> 8;
            int kp  = n & 255;
            int token = __ldg(&seq[r32 * SS + 0]);
            preg[i] = __ldg((const unsigned long long*)
                            (emb_table + (size_t)token * EE) + kp);
        }
        #pragma unroll
        for (int i = 0; i < 16; i++) {
            int n = i * NTHR + tid;
            x_sh[(n & 255) * 33 + (n >> 8)] = preg[i];
        }
        __syncthreads();
    }

    unsigned long long acc[16];
    {
        unsigned long long x[16];
        #pragma unroll
        for (int i = 0; i < 16; i++) x[i] = x_sh[(ks * 16 + i) * 33 + b];
        #pragma unroll
        for (int r = 0; r < 16; r++) acc[r] = 0ull;
        #pragma unroll
        for (int i2 = 0; i2 < 8; i2++) {
            unsigned long long xa = x[2 * i2], xb = x[2 * i2 + 1];
            #pragma unroll
            for (int r = 0; r < 16; r++) {
                ulonglong2 wv = *(const ulonglong2*)(w2_sh + r * 512 + ks * 16 + 2 * i2);
                acc[r] = ffma2u(xa, wv.x, ffma2u(xb, wv.y, acc[r]));
            }
        }
        #pragma unroll
        for (int i = 0; i < 16; i++) {
            int n  = i * NTHR + tid;
            int r32 = n >> 8;
            int kp  = n & 255;
            int token = __ldg(&seq[r32 * SS + 1]);
            preg[i] = __ldg((const unsigned long long*)
                            (emb_table + (size_t)token * EE) + kp);
        }
    }

    const bool is_red = (tid >= 384);
    const int  u  = tid - 384;
    const int  jj = u >> 5;
    const int  bb = u & 31;

    for (int t = 0; t < SS; t++) {
        if (t > 0) {
            // hierarchical wait: thread i polls counter i for >= 8t
            if (tid < 16) {
                unsigned target = 8u * (unsigned)t;
                while (ld_acq(&g_gen16[tid]) < target) { }
            }
            __syncthreads();   // BAR A: all 16 counters passed -> h(t-1) visible
        }

        // stage x_emb with tokens for step t+1
        if (t + 1 < SS) {
            #pragma unroll
            for (int i = 0; i < 16; i++) {
                int n = i * NTHR + tid;
                x_sh[(n & 255) * 33 + (n >> 8)] = preg[i];
            }
        }

        // recurrent half accumulates onto emb partials already in acc
        if (t > 0) {
            unsigned long long x[16];
            const unsigned long long* hb = &g_ht2[(t - 1) & 1][ks * 16][0];
            #pragma unroll
            for (int i = 0; i < 16; i++) x[i] = __ldcg(&hb[i * BB + b]);
            #pragma unroll
            for (int i2 = 0; i2 < 8; i2++) {
                unsigned long long xa = x[2 * i2], xb = x[2 * i2 + 1];
                #pragma unroll
                for (int r = 0; r < 16; r++) {
                    ulonglong2 wv = *(const ulonglong2*)
                        (w2_sh + r * 512 + 256 + ks * 16 + 2 * i2);
                    acc[r] = ffma2u(xa, wv.x, ffma2u(xb, wv.y, acc[r]));
                }
            }
        }
        #pragma unroll
        for (int r = 0; r < 16; r++) {
            F2U a; a.u = acc[r];
            partf[r * 512 + ks * 32 + b] = a.f.x + a.f.y;
        }
        __syncthreads();   // BAR B: partf + x_emb staged

        if (is_red) {
            float gs[4];
            #pragma unroll
            for (int g = 0; g < 4; g++) {
                int r = g * 4 + jj;
                float s = 0.f;
                #pragma unroll
                for (int k2 = 0; k2 < 16; k2++) s += partf[r * 512 + k2 * 32 + bb];
                gs[g] = s + cns_sh[r * BB + bb];
            }
            float ig = fast_sigmoid(gs[0]);
            float fg = fast_sigmoid(gs[1]);
            float gg = fast_tanh(gs[2]);
            float og = fast_sigmoid(gs[3]);
            float cc = fg * c0_sh[jj * BB + bb] + ig * gg;
            float hh = og * fast_tanh(cc);

            float* hp = (float*)&g_ht2[t & 1][2 * bid + (jj >> 1)][bb];
            hp[jj & 1] = hh;
            asm volatile("bar.sync 1, 128;" ::: "memory");
            if (tid == 511) red_release_add(&g_gen16[bid & 15], 1u);
            out[(size_t)bb * (SS * HH) + (size_t)t * HH + j0 + jj] = hh;
        }

        // emb-FMA for step t+1 (overlaps reducers' reduce/publish)
        if (t + 1 < SS) {
            unsigned long long x[16];
            #pragma unroll
            for (int i = 0; i < 16; i++) x[i] = x_sh[(ks * 16 + i) * 33 + b];
            #pragma unroll
            for (int r = 0; r < 16; r++) acc[r] = 0ull;
            #pragma unroll
            for (int i2 = 0; i2 < 8; i2++) {
                unsigned long long xa = x[2 * i2], xb = x[2 * i2 + 1];
                #pragma unroll
                for (int r = 0; r < 16; r++) {
                    ulonglong2 wv = *(const ulonglong2*)
                        (w2_sh + r * 512 + ks * 16 + 2 * i2);
                    acc[r] = ffma2u(xa, wv.x, ffma2u(xb, wv.y, acc[r]));
                }
            }
            if (t + 2 < SS) {
                #pragma unroll
                for (int i = 0; i < 16; i++) {
                    int n  = i * NTHR + tid;
                    int r32 = n >> 8;
                    int kp  = n & 255;
                    int token = __ldg(&seq[r32 * SS + t + 2]);
                    preg[i] = __ldg((const unsigned long long*)
                                    (emb_table + (size_t)token * EE) + kp);
                }
            }
        }
    }
}

extern "C" void kernel_launch(void* const* d_in, const int* in_sizes, int n_in,
                              void* d_out, int out_size) {
    const int*   seq   = (const int*)d_in[0];
    // d_in[1] = enc_out : unused
    const float* enc_h = (const float*)d_in[2];
    const float* enc_c = (const float*)d_in[3];
    const float* emb   = (const float*)d_in[4];
    const float* W_ih  = (const float*)d_in[5];
    const float* W_hh  = (const float*)d_in[6];
    const float* b_ih  = (const float*)d_in[7];
    const float* b_hh  = (const float*)d_in[8];
    float* out = (float*)d_out;

    static bool attr_set = false;
    if (!attr_set) {
        cudaFuncSetAttribute(lstm_fused_kernel,
                             cudaFuncAttributeMaxDynamicSharedMemorySize, SMEM_TOT);
        attr_set = true;
    }

    reset_gen_kernel<<<1, 32>>>();
    lstm_fused_kernel<<<128, NTHR, SMEM_TOT>>>(seq, enc_h, enc_c, emb,
                                               W_ih, W_hh, b_ih, b_hh, out);
}

// round 15
// speedup vs baseline: 2.0880x; 1.0108x over previous
#include <cuda_runtime.h>
#include <math.h>

#define BB   32
#define SS   512
#define HH   512
#define EE   512
#define JPB  4
#define NTHR 512

// ---------- global scratch ----------
__device__ unsigned long long g_ht2[2][256][BB];   // [buf][jpair][b]
__device__ unsigned g_gen16[16];                    // counter g: CTAs [8g, 8g+8)

union F2U { unsigned long long u; float2 f; };

__device__ __forceinline__ unsigned long long ffma2u(unsigned long long a,
                                                     unsigned long long b,
                                                     unsigned long long c) {
    unsigned long long d;
    asm("fma.rn.f32x2 %0, %1, %2, %3;" : "=l"(d) : "l"(a), "l"(b), "l"(c));
    return d;
}

__device__ __forceinline__ unsigned ld_acq(const unsigned* p) {
    unsigned v;
    asm volatile("ld.global.acquire.gpu.u32 %0, [%1];" : "=r"(v) : "l"(p) : "memory");
    return v;
}
__device__ __forceinline__ void red_release_add(unsigned* p, unsigned v) {
    asm volatile("red.release.gpu.global.add.u32 [%0], %1;" :: "l"(p), "r"(v) : "memory");
}

__device__ __forceinline__ float fast_sigmoid(float x) {
    return __fdividef(1.0f, 1.0f + __expf(-x));
}
__device__ __forceinline__ float fast_tanh(float x) {
    return __fdividef(2.0f, 1.0f + __expf(-2.0f * x)) - 1.0f;
}

__global__ void reset_gen_kernel() {
    if (threadIdx.x < 16) g_gen16[threadIdx.x] = 0u;
}

// ======================================================================
// Fused persistent LSTM, per-warp decoupled wait:
// 128 CTAs x 512 threads. CTA bid owns h[4bid..4bid+3] (16 gate rows).
// Warp ks (K-chunk [32ks,32ks+32)) polls ONLY counter ks (its 8 producers),
// lane 0 + __syncwarp -> starts gather+rec-FMA immediately. One CTA-wide
// __syncthreads (BAR B) per step ANDs all warps/counters (preserves global
// transitivity for all buffer reuse). x_sh double-buffered + XOR swizzle.
// ======================================================================
#define OFF_W    0          // 16*512 u64 = 65536
#define OFF_PART 65536      // 16*512 f32 = 32768
#define OFF_X    98304      // 2 * 8192 u64 = 131072 (XOR-swizzled, no pad)
#define OFF_CNS  229376     // 16*32 f32 = 2048
#define OFF_C0   231424     // 4*32 f32 = 512
#define SMEM_TOT 231936

__global__ __launch_bounds__(NTHR, 1)
void lstm_fused_kernel(const int* __restrict__ seq,
                       const float* __restrict__ enc_h,
                       const float* __restrict__ enc_c,
                       const float* __restrict__ emb_table,
                       const float* __restrict__ W_ih,
                       const float* __restrict__ W_hh,
                       const float* __restrict__ b_ih,
                       const float* __restrict__ b_hh,
                       float* __restrict__ out)
{
    extern __shared__ char smem[];
    unsigned long long* w2_sh  = (unsigned long long*)(smem + OFF_W);
    float*              partf  = (float*)(smem + OFF_PART);
    unsigned long long* x_sh   = (unsigned long long*)(smem + OFF_X);  // [buf][8192]
    float*              cns_sh = (float*)(smem + OFF_CNS);
    float*              c0_sh  = (float*)(smem + OFF_C0);

    const int tid = threadIdx.x;
    const int bid = blockIdx.x;
    const int ks  = tid >> 5;
    const int b   = tid & 31;
    const int j0  = bid * JPB;

    // ---- stage FULL W_ih rows (emb pairs 0..255, rec pairs 256..511) ----
    for (int idx = tid; idx < 16 * 512; idx += NTHR) {
        int r  = idx >> 9;
        int kp = idx & 511;
        int grow = (r >> 2) * HH + j0 + (r & 3);
        w2_sh[idx] = ((const unsigned long long*)(W_ih + (size_t)grow * (EE + HH)))[kp];
    }
    if (tid < 128) c0_sh[(tid >> 5) * BB + b] = enc_c[b * HH + j0 + (tid >> 5)];
    __syncthreads();

    // ---- const = h0 @ W_hh^T + b_ih + b_hh (partf as scratch) ----
    {
        float h0c[32];
        #pragma unroll
        for (int i = 0; i < 32; i++) h0c[i] = enc_h[b * HH + ks * 32 + i];
        #pragma unroll
        for (int r = 0; r < 16; r++) {
            const float* wr = W_hh + (size_t)((r >> 2) * HH + j0 + (r & 3)) * HH + ks * 32;
            float acc = 0.f;
            #pragma unroll
            for (int i = 0; i < 32; i++) acc = fmaf(h0c[i], wr[i], acc);
            partf[r * 512 + ks * 32 + b] = acc;
        }
        __syncthreads();
        {
            float s = 0.f;
            #pragma unroll
            for (int k2 = 0; k2 < 16; k2++) s += partf[ks * 512 + k2 * 32 + b];
            int grow = (ks >> 2) * HH + j0 + (ks & 3);
            cns_sh[ks * BB + b] = s + b_ih[grow] + b_hh[grow];
        }
        __syncthreads();
    }

    // ---- prologue: buf1 <- tokens(0); emb-FMA(0) -> acc; preg <- tokens(1) ----
    unsigned long long preg[16];
    {
        #pragma unroll
        for (int i = 0; i < 16; i++) {
            int n   = i * NTHR + tid;
            int r32 = n >> 8;
            int kp  = n & 255;
            int token = __ldg(&seq[r32 * SS + 0]);
            x_sh[8192 + kp * 32 + (r32 ^ (kp & 31))] = __ldg(
                (const unsigned long long*)(emb_table + (size_t)token * EE) + kp);
        }
        __syncthreads();
    }

    unsigned long long acc[16];
    {
        unsigned long long x[16];
        #pragma unroll
        for (int i = 0; i < 16; i++) {
            int kp = ks * 16 + i;
            x[i] = x_sh[8192 + kp * 32 + (b ^ (kp & 31))];
        }
        #pragma unroll
        for (int r = 0; r < 16; r++) acc[r] = 0ull;
        #pragma unroll
        for (int i2 = 0; i2 < 8; i2++) {
            unsigned long long xa = x[2 * i2], xb = x[2 * i2 + 1];
            #pragma unroll
            for (int r = 0; r < 16; r++) {
                ulonglong2 wv = *(const ulonglong2*)(w2_sh + r * 512 + ks * 16 + 2 * i2);
                acc[r] = ffma2u(xa, wv.x, ffma2u(xb, wv.y, acc[r]));
            }
        }
        #pragma unroll
        for (int i = 0; i < 16; i++) {
            int n   = i * NTHR + tid;
            int r32 = n >> 8;
            int kp  = n & 255;
            int token = __ldg(&seq[r32 * SS + 1]);
            preg[i] = __ldg((const unsigned long long*)
                            (emb_table + (size_t)token * EE) + kp);
        }
    }

    const bool is_red = (tid >= 384);
    const int  u  = tid - 384;
    const int  jj = u >> 5;
    const int  bb = u & 31;

    for (int t = 0; t < SS; t++) {
        // ---- per-warp wait + gather + rec-FMA ----
        if (t > 0) {
            if ((tid & 31) == 0) {
                unsigned target = 8u * (unsigned)t;
                while (ld_acq(&g_gen16[ks]) < target) { }
            }
            __syncwarp();
            unsigned long long x[16];
            const unsigned long long* hb = &g_ht2[(t - 1) & 1][ks * 16][0];
            #pragma unroll
            for (int i = 0; i < 16; i++) x[i] = __ldcg(&hb[i * BB + b]);
            #pragma unroll
            for (int i2 = 0; i2 < 8; i2++) {
                unsigned long long xa = x[2 * i2], xb = x[2 * i2 + 1];
                #pragma unroll
                for (int r = 0; r < 16; r++) {
                    ulonglong2 wv = *(const ulonglong2*)
                        (w2_sh + r * 512 + 256 + ks * 16 + 2 * i2);
                    acc[r] = ffma2u(xa, wv.x, ffma2u(xb, wv.y, acc[r]));
                }
            }
        }
        #pragma unroll
        for (int r = 0; r < 16; r++) {
            F2U a; a.u = acc[r];
            partf[r * 512 + ks * 32 + b] = a.f.x + a.f.y;
        }

        // ---- stage x_emb (tokens t+1) into buf t&1 ----
        if (t + 1 < SS) {
            unsigned long long* xb = x_sh + (t & 1) * 8192;
            #pragma unroll
            for (int i = 0; i < 16; i++) {
                int n   = i * NTHR + tid;
                int r32 = n >> 8;
                int kp  = n & 255;
                xb[kp * 32 + (r32 ^ (kp & 31))] = preg[i];
            }
        }
        __syncthreads();   // BAR B: partf + x_emb ready; ANDs all 16 warp-polls

        if (is_red) {
            float gs[4];
            #pragma unroll
            for (int g = 0; g < 4; g++) {
                int r = g * 4 + jj;
                float s = 0.f;
                #pragma unroll
                for (int k2 = 0; k2 < 16; k2++) s += partf[r * 512 + k2 * 32 + bb];
                gs[g] = s + cns_sh[r * BB + bb];
            }
            float ig = fast_sigmoid(gs[0]);
            float fg = fast_sigmoid(gs[1]);
            float gg = fast_tanh(gs[2]);
            float og = fast_sigmoid(gs[3]);
            float cc = fg * c0_sh[jj * BB + bb] + ig * gg;
            float hh = og * fast_tanh(cc);

            float* hp = (float*)&g_ht2[t & 1][2 * bid + (jj >> 1)][bb];
            hp[jj & 1] = hh;
            asm volatile("bar.sync 1, 128;" ::: "memory");
            if (tid == 511) red_release_add(&g_gen16[bid >> 3], 1u);
            out[(size_t)bb * (SS * HH) + (size_t)t * HH + j0 + jj] = hh;
        }

        // ---- emb-FMA for step t+1 (reads buf t&1) + preg LDG (tokens t+2) ----
        if (t + 1 < SS) {
            const unsigned long long* xb = x_sh + (t & 1) * 8192;
            unsigned long long x[16];
            #pragma unroll
            for (int i = 0; i < 16; i++) {
                int kp = ks * 16 + i;
                x[i] = xb[kp * 32 + (b ^ (kp & 31))];
            }
            #pragma unroll
            for (int r = 0; r < 16; r++) acc[r] = 0ull;
            #pragma unroll
            for (int i2 = 0; i2 < 8; i2++) {
                unsigned long long xa = x[2 * i2], xb2 = x[2 * i2 + 1];
                #pragma unroll
                for (int r = 0; r < 16; r++) {
                    ulonglong2 wv = *(const ulonglong2*)
                        (w2_sh + r * 512 + ks * 16 + 2 * i2);
                    acc[r] = ffma2u(xa, wv.x, ffma2u(xb2, wv.y, acc[r]));
                }
            }
            if (t + 2 < SS) {
                #pragma unroll
                for (int i = 0; i < 16; i++) {
                    int n   = i * NTHR + tid;
                    int r32 = n >> 8;
                    int kp  = n & 255;
                    int token = __ldg(&seq[r32 * SS + t + 2]);
                    preg[i] = __ldg((const unsigned long long*)
                                    (emb_table + (size_t)token * EE) + kp);
                }
            }
        }
    }
}

extern "C" void kernel_launch(void* const* d_in, const int* in_sizes, int n_in,
                              void* d_out, int out_size) {
    const int*   seq   = (const int*)d_in[0];
    // d_in[1] = enc_out : unused
    const float* enc_h = (const float*)d_in[2];
    const float* enc_c = (const float*)d_in[3];
    const float* emb   = (const float*)d_in[4];
    const float* W_ih  = (const float*)d_in[5];
    const float* W_hh  = (const float*)d_in[6];
    const float* b_ih  = (const float*)d_in[7];
    const float* b_hh  = (const float*)d_in[8];
    float* out = (float*)d_out;

    static bool attr_set = false;
    if (!attr_set) {
        cudaFuncSetAttribute(lstm_fused_kernel,
                             cudaFuncAttributeMaxDynamicSharedMemorySize, SMEM_TOT);
        attr_set = true;
    }

    reset_gen_kernel<<<1, 32>>>();
    lstm_fused_kernel<<<128, NTHR, SMEM_TOT>>>(seq, enc_h, enc_c, emb,
                                               W_ih, W_hh, b_ih, b_hh, out);
}